// round 2
// baseline (speedup 1.0000x reference)
#include <cuda_runtime.h>
#include <stdint.h>

// Problem constants (fixed benchmark): N=1e6, IN_C=OUT_C=64, FEAT_C=128, G=4096
#define N_MAX 1000000
#define G_MAX 4096

// Scratch (static device allocations are allowed)
__device__ int   d_count[G_MAX];
__device__ int   d_offsets[G_MAX + 1];
__device__ int   d_cursor[G_MAX];
__device__ int   d_order[N_MAX];
__device__ float d_mu[G_MAX * 64];
__device__ float d_sig[G_MAX * 64];

// ---------------------------------------------------------------------------
__global__ void init_kernel(int G) {
    int i = blockIdx.x * blockDim.x + threadIdx.x;
    if (i < G) d_count[i] = 0;
}

__global__ void hist_kernel(const int* __restrict__ seg, int n) {
    int i = blockIdx.x * blockDim.x + threadIdx.x;
    if (i < n) atomicAdd(&d_count[seg[i]], 1);
}

// Single-CTA scan of up to 4096 counts (1024 threads x 4 each)
__global__ void scan_kernel(int G) {
    __shared__ int s[1024];
    int t = threadIdx.x;
    int v[4];
    int sum = 0;
#pragma unroll
    for (int i = 0; i < 4; i++) {
        int g = 4 * t + i;
        v[i] = (g < G) ? d_count[g] : 0;
        sum += v[i];
    }
    s[t] = sum;
    __syncthreads();
    for (int off = 1; off < 1024; off <<= 1) {
        int x = (t >= off) ? s[t - off] : 0;
        __syncthreads();
        s[t] += x;
        __syncthreads();
    }
    int excl = s[t] - sum;
#pragma unroll
    for (int i = 0; i < 4; i++) {
        int g = 4 * t + i;
        if (g < G) {
            d_offsets[g] = excl;
            d_cursor[g]  = excl;
            excl += v[i];
        }
    }
    if (t == 1023) d_offsets[G] = s[1023];
}

__global__ void scatter_kernel(const int* __restrict__ seg, int n) {
    int i = blockIdx.x * blockDim.x + threadIdx.x;
    if (i < n) {
        int p = atomicAdd(&d_cursor[seg[i]], 1);
        d_order[p] = i;
    }
}

// mu = origin_feat @ W_mu + b_mu ; sig = origin_feat @ W_sig + b_sig
// 4 groups per CTA, 256 threads: thread -> (group-local gl, channel c)
__global__ void musig_kernel(const float* __restrict__ feat,
                             const float* __restrict__ Wmu, const float* __restrict__ bmu,
                             const float* __restrict__ Wsg, const float* __restrict__ bsg,
                             int G) {
    __shared__ float sF[4][128];
    int t  = threadIdx.x;
    int g0 = blockIdx.x * 4;
    for (int i = t; i < 512; i += 256) {
        int gl = i >> 7, k = i & 127;
        int g  = g0 + gl;
        sF[gl][k] = (g < G) ? feat[(size_t)g * 128 + k] : 0.f;
    }
    __syncthreads();
    int gl = t >> 6, c = t & 63;
    int g  = g0 + gl;
    if (g >= G) return;
    float am = bmu[c], as = bsg[c];
#pragma unroll 4
    for (int k = 0; k < 128; k++) {
        float f = sF[gl][k];
        am = fmaf(f, Wmu[k * 64 + c], am);
        as = fmaf(f, Wsg[k * 64 + c], as);
    }
    d_mu[(size_t)g * 64 + c]  = am;
    d_sig[(size_t)g * 64 + c] = as;
}

// ---------------------------------------------------------------------------
// Per-group fused kernel: gather x rows -> GEMM (4x4 register tile/thread)
// -> in-register stats -> scale/shift -> write out.  h cached in SMEM
// (CAP rows); groups larger than CAP take a recompute fallback.
// SMEM rows use a float4 rotation swizzle: element (row,k) lives at column
// (k + 4*(row&15)) & 63 -> conflict-free for k-major and c-major access.
// ---------------------------------------------------------------------------
#define CAP 320          // cached h rows (5 chunks of 64)
#define CHUNK 64

struct SmemLayout {
    // sW: 4096 floats, sH: CAP*64, then 6*64 stats floats
};

__device__ __forceinline__ void chunk_gemm(const float* __restrict__ sH,
                                           const float* __restrict__ sW,
                                           const float bf[4],
                                           int slot, int rb, int cb,
                                           float acc[4][4]) {
#pragma unroll
    for (int r = 0; r < 4; r++) {
        acc[r][0] = bf[0]; acc[r][1] = bf[1]; acc[r][2] = bf[2]; acc[r][3] = bf[3];
    }
    const float* rowp[4];
    int rot4[4];
#pragma unroll
    for (int r = 0; r < 4; r++) {
        int lr  = rb * 4 + r;            // local row in chunk (0..63)
        rowp[r] = sH + (size_t)(slot + lr) * 64;
        rot4[r] = lr & 15;               // float4 rotation
    }
#pragma unroll 4
    for (int k4 = 0; k4 < 16; k4++) {
        float4 xv[4];
#pragma unroll
        for (int r = 0; r < 4; r++) {
            int f = (k4 + rot4[r]) & 15;
            xv[r] = reinterpret_cast<const float4*>(rowp[r])[f];
        }
#pragma unroll
        for (int kk = 0; kk < 4; kk++) {
            int k     = k4 * 4 + kk;
            float4 w4 = reinterpret_cast<const float4*>(sW + k * 64)[cb];
#pragma unroll
            for (int r = 0; r < 4; r++) {
                float xk = (kk == 0) ? xv[r].x : (kk == 1) ? xv[r].y : (kk == 2) ? xv[r].z : xv[r].w;
                acc[r][0] = fmaf(xk, w4.x, acc[r][0]);
                acc[r][1] = fmaf(xk, w4.y, acc[r][1]);
                acc[r][2] = fmaf(xk, w4.z, acc[r][2]);
                acc[r][3] = fmaf(xk, w4.w, acc[r][3]);
            }
        }
    }
}

__device__ __forceinline__ void stage_chunk(float* __restrict__ sH,
                                            const float* __restrict__ x,
                                            int off, int base, int slot,
                                            int cnt, int sr, int sq) {
    int gr = base + sr;                       // group-local row
    int ra = slot + sr;                       // smem row
    float4 v[4];
    if (gr < cnt) {
        int gi = d_order[off + gr];
        const float4* xr = reinterpret_cast<const float4*>(x + (size_t)gi * 64);
#pragma unroll
        for (int i = 0; i < 4; i++) v[i] = xr[sq * 4 + i];
    } else {
#pragma unroll
        for (int i = 0; i < 4; i++) v[i] = make_float4(0.f, 0.f, 0.f, 0.f);
    }
    float4* row4 = reinterpret_cast<float4*>(sH + (size_t)ra * 64);
    int rot = sr & 15;                        // slot is multiple of 64
#pragma unroll
    for (int i = 0; i < 4; i++) row4[(sq * 4 + i + rot) & 15] = v[i];
}

__global__ __launch_bounds__(256, 2) void group_kernel(const float* __restrict__ x,
                                                       const float* __restrict__ Wfc,
                                                       const float* __restrict__ bfc,
                                                       float* __restrict__ out) {
    extern __shared__ float sm[];
    float* sW     = sm;                 // 4096
    float* sH     = sm + 4096;          // CAP*64
    float* sSum   = sH + CAP * 64;      // 64
    float* sSq    = sSum + 64;          // 64
    float* sMu    = sSq + 64;           // 64
    float* sSig   = sMu + 64;           // 64
    float* sScale = sSig + 64;          // 64
    float* sShift = sScale + 64;        // 64

    int t   = threadIdx.x;
    int g   = blockIdx.x;
    int off = d_offsets[g];
    int cnt = d_offsets[g + 1] - off;

    for (int i = t; i < 4096; i += 256) sW[i] = Wfc[i];
    if (t < 64) {
        sMu[t]  = d_mu[(size_t)g * 64 + t];
        sSig[t] = d_sig[(size_t)g * 64 + t];
        sSum[t] = 0.f;
        sSq[t]  = 0.f;
    }
    int rb = t >> 4, cb = t & 15;
    float bf[4];
    {
        float4 b4 = reinterpret_cast<const float4*>(bfc)[cb];
        bf[0] = b4.x; bf[1] = b4.y; bf[2] = b4.z; bf[3] = b4.w;
    }
    __syncthreads();
    if (cnt == 0) return;

    bool cached = (cnt <= CAP);
    int  nch    = (cnt + CHUNK - 1) >> 6;
    int  sr = t >> 2, sq = t & 3;      // staging: row, quarter

    float csum[4] = {0.f, 0.f, 0.f, 0.f};
    float csq[4]  = {0.f, 0.f, 0.f, 0.f};
    float acc[4][4];

    // -------- pass 1: GEMM + stats (+ cache h) --------
    for (int c = 0; c < nch; c++) {
        int base = c << 6;
        int slot = cached ? base : 0;
        stage_chunk(sH, x, off, base, slot, cnt, sr, sq);
        __syncthreads();
        chunk_gemm(sH, sW, bf, slot, rb, cb, acc);
#pragma unroll
        for (int r = 0; r < 4; r++) {
            if (base + rb * 4 + r < cnt) {
#pragma unroll
                for (int j = 0; j < 4; j++) {
                    float h = acc[r][j];
                    csum[j] += h;
                    csq[j]   = fmaf(h, h, csq[j]);
                }
            }
        }
        __syncthreads();                  // all x reads of this slot done
        if (cached) {
#pragma unroll
            for (int r = 0; r < 4; r++) {
                int lr = rb * 4 + r;
                reinterpret_cast<float4*>(sH + (size_t)(slot + lr) * 64)[(cb + (lr & 15)) & 15] =
                    make_float4(acc[r][0], acc[r][1], acc[r][2], acc[r][3]);
            }
        }
    }

    // -------- reduce stats --------
    unsigned full = 0xffffffffu;
#pragma unroll
    for (int j = 0; j < 4; j++) {
        csum[j] += __shfl_down_sync(full, csum[j], 16);
        csq[j]  += __shfl_down_sync(full, csq[j], 16);
    }
    if ((t & 31) < 16) {
#pragma unroll
        for (int j = 0; j < 4; j++) {
            atomicAdd(&sSum[cb * 4 + j], csum[j]);
            atomicAdd(&sSq[cb * 4 + j], csq[j]);
        }
    }
    __syncthreads();

    if (t < 64) {
        float inv_n = 1.0f / (float)cnt;
        float mean  = sSum[t] * inv_n;
        float var   = sSq[t] * inv_n - mean * mean;
        var = fmaxf(var, 0.f);
        float sc = sSig[t] * rsqrtf(var + 1e-14f);
        sScale[t] = sc;
        sShift[t] = sMu[t] - mean * sc;
    }
    __syncthreads();

    // -------- pass 2: apply + write --------
    if (cached) {
        int w = t >> 5, l = t & 31;
        float2 sc2 = reinterpret_cast<float2*>(sScale)[l];
        float2 sh2 = reinterpret_cast<float2*>(sShift)[l];
        for (int j = w; j < cnt; j += 8) {
            int gi  = d_order[off + j];
            int col = (2 * l + 4 * (j & 15)) & 63;
            float2 h2 = *reinterpret_cast<float2*>(&sH[(size_t)j * 64 + col]);
            float2 o;
            o.x = fmaxf(fmaf(h2.x, sc2.x, sh2.x), 0.f);
            o.y = fmaxf(fmaf(h2.y, sc2.y, sh2.y), 0.f);
            reinterpret_cast<float2*>(out + (size_t)gi * 64)[l] = o;
        }
    } else {
        // rare: recompute h per chunk and write directly
        float4 sc4 = reinterpret_cast<float4*>(sScale)[cb];
        float4 sh4 = reinterpret_cast<float4*>(sShift)[cb];
        for (int c = 0; c < nch; c++) {
            int base = c << 6;
            stage_chunk(sH, x, off, base, 0, cnt, sr, sq);
            __syncthreads();
            chunk_gemm(sH, sW, bf, 0, rb, cb, acc);
#pragma unroll
            for (int r = 0; r < 4; r++) {
                int gr = base + rb * 4 + r;
                if (gr < cnt) {
                    int gi = d_order[off + gr];
                    float4 o;
                    o.x = fmaxf(fmaf(acc[r][0], sc4.x, sh4.x), 0.f);
                    o.y = fmaxf(fmaf(acc[r][1], sc4.y, sh4.y), 0.f);
                    o.z = fmaxf(fmaf(acc[r][2], sc4.z, sh4.z), 0.f);
                    o.w = fmaxf(fmaf(acc[r][3], sc4.w, sh4.w), 0.f);
                    reinterpret_cast<float4*>(out + (size_t)gi * 64)[cb] = o;
                }
            }
            __syncthreads();              // reads done before next staging
        }
    }
}

// ---------------------------------------------------------------------------
extern "C" void kernel_launch(void* const* d_in, const int* in_sizes, int n_in,
                              void* d_out, int out_size) {
    // inputs: x, origin_feat, latent_point_batch, [num_groups], W_fc, b_fc,
    //         W_mu, b_mu, W_sig, b_sig
    int wi = (n_in >= 10) ? 4 : 3;
    const float* x    = (const float*)d_in[0];
    const float* feat = (const float*)d_in[1];
    const int*   seg  = (const int*)d_in[2];
    const float* Wfc  = (const float*)d_in[wi + 0];
    const float* bfc  = (const float*)d_in[wi + 1];
    const float* Wmu  = (const float*)d_in[wi + 2];
    const float* bmu  = (const float*)d_in[wi + 3];
    const float* Wsg  = (const float*)d_in[wi + 4];
    const float* bsg  = (const float*)d_in[wi + 5];
    float* out = (float*)d_out;

    int n = in_sizes[0] / 64;
    int G = in_sizes[1] / 128;

    const size_t smem = (size_t)(4096 + CAP * 64 + 6 * 64) * sizeof(float); // 99840 B
    cudaFuncSetAttribute(group_kernel, cudaFuncAttributeMaxDynamicSharedMemorySize,
                         (int)smem);

    init_kernel<<<(G + 255) / 256, 256>>>(G);
    musig_kernel<<<(G + 3) / 4, 256>>>(feat, Wmu, bmu, Wsg, bsg, G);
    hist_kernel<<<(n + 255) / 256, 256>>>(seg, n);
    scan_kernel<<<1, 1024>>>(G);
    scatter_kernel<<<(n + 255) / 256, 256>>>(seg, n);
    group_kernel<<<G, 256, smem>>>(x, Wfc, bfc, out);
}